// round 15
// baseline (speedup 1.0000x reference)
#include <cuda_runtime.h>
#include <cuda_bf16.h>
#include <cstdint>

// ---------------------------------------------------------------------------
// CompressedGNN on GB300 (plain sm_103 target — no tcgen05 in harness PTX).
// GEMMs: mma.sync bf16 (HMMA), split-precision x3 fused, BM=64 @ 3 CTAs/SM.
// Graph: bucketed adjacency (no count/scan) built inside the prep mega-kernel.
// cnt re-zeroed by agg phase-1 for graph replay. 6 launches total.
// ---------------------------------------------------------------------------

#define NNODES 10000
#define MAXE   160000
#define DH     512
#define NPADC  128
#define CAP    96                 // per-node bucket capacity (max indeg ~35)

__device__ float g_h[NNODES * DH];              // fp32 GEMM output
__device__ uint4 g_ahi[NNODES * DH / 8];        // split A operand (8 bf16/uint4)
__device__ uint4 g_alo[NNODES * DH / 8];
__device__ uint4 g_w1hi[DH * DH / 8];           // transposed split weights [N][K]
__device__ uint4 g_w1lo[DH * DH / 8];
__device__ uint4 g_w2hi[DH * DH / 8];
__device__ uint4 g_w2lo[DH * DH / 8];
__device__ uint4 g_wchi[NPADC * DH / 8];
__device__ uint4 g_wclo[NPADC * DH / 8];
__device__ float g_dinv[NNODES];
__device__ int   g_cnt[NNODES];                 // zero-init; re-zeroed by agg ph1
__device__ int   g_col[NNODES * CAP];

// ---------------------------------------------------------------------------
__device__ __forceinline__ uint32_t smem_to_u32(const void* p) {
    uint32_t a;
    asm("{ .reg .u64 t; cvta.to.shared.u64 t, %1; cvt.u32.u64 %0, t; }"
        : "=r"(a) : "l"(p));
    return a;
}

__device__ __forceinline__ void ldmat_x4(uint32_t (&r)[4], uint32_t addr) {
    asm volatile("ldmatrix.sync.aligned.m8n8.x4.shared.b16 {%0,%1,%2,%3}, [%4];"
                 : "=r"(r[0]), "=r"(r[1]), "=r"(r[2]), "=r"(r[3]) : "r"(addr));
}

__device__ __forceinline__ void mma_bf16(float (&d)[4], const uint32_t (&a)[4],
                                         uint32_t b0, uint32_t b1) {
    asm volatile("mma.sync.aligned.m16n8k16.row.col.f32.bf16.bf16.f32 "
                 "{%0,%1,%2,%3}, {%4,%5,%6,%7}, {%8,%9}, {%0,%1,%2,%3};"
                 : "+f"(d[0]), "+f"(d[1]), "+f"(d[2]), "+f"(d[3])
                 : "r"(a[0]), "r"(a[1]), "r"(a[2]), "r"(a[3]), "r"(b0), "r"(b1));
}

__device__ __forceinline__ void cp16(uint32_t dst, const void* src, bool valid) {
    int sz = valid ? 16 : 0;
    asm volatile("cp.async.cg.shared.global [%0], [%1], 16, %2;"
                 :: "r"(dst), "l"(src), "r"(sz) : "memory");
}
#define CP_COMMIT() asm volatile("cp.async.commit_group;" ::: "memory")
#define CP_WAIT0()  asm volatile("cp.async.wait_group 0;" ::: "memory")
#define CP_WAIT1()  asm volatile("cp.async.wait_group 1;" ::: "memory")

// ---------------------------------------------------------------------------
__device__ __forceinline__ void split_bf16(float v, __nv_bfloat16& hi, __nv_bfloat16& lo) {
    hi = __float2bfloat16(v);
    lo = __float2bfloat16(v - __bfloat162float(hi));
}

// ---------------------------------------------------------------------------
// Merged prep:
//   [0, 2500)            conv_x: split x into g_ahi/g_alo
//   [2500, 3125)         fill: bucketed adjacency (g_cnt was left zeroed)
//   [3125, 3701)         weight transpose + split
// ---------------------------------------------------------------------------
#define CONV_BLOCKS 2500
#define FILL_BLOCKS 625
#define W1_TILES 256
#define W2_TILES 256
#define WC_TILES 64
#define PREP_BLOCKS (CONV_BLOCKS + FILL_BLOCKS + W1_TILES + W2_TILES + WC_TILES)

__global__ __launch_bounds__(256) void prep_all_kernel(
    const float* __restrict__ x, const int* __restrict__ ei, int E,
    const float* __restrict__ W1, const float* __restrict__ W2,
    const float* __restrict__ Wc, int NcOut)
{
    int b = blockIdx.x, tid = threadIdx.x;

    if (b < CONV_BLOCKS) {
        int idx = b * 256 + tid;
        const float4* p = (const float4*)x;
        float4 a = p[idx * 2], b4 = p[idx * 2 + 1];
        float v[8] = {a.x, a.y, a.z, a.w, b4.x, b4.y, b4.z, b4.w};
        __nv_bfloat16 hi[8], lo[8];
#pragma unroll
        for (int j = 0; j < 8; ++j) split_bf16(v[j], hi[j], lo[j]);
        g_ahi[idx] = *(uint4*)hi;
        g_alo[idx] = *(uint4*)lo;
        return;
    }
    b -= CONV_BLOCKS;
    if (b < FILL_BLOCKS) {
        int e = b * 256 + tid;
        if (e < E) {
            int s = ei[e];
            int d = ei[E + e];
            if (d >= 0 && d < NNODES && s >= 0 && s < NNODES) {
                int pos = atomicAdd(&g_cnt[d], 1);
                if (pos < CAP) g_col[(size_t)d * CAP + pos] = s;
            }
        }
        return;
    }
    b -= FILL_BLOCKS;

    // weight transpose + split, 32x32 tile per block, 256 threads (4 rows each)
    int which, tileIdx, ntn;
    if (b < W1_TILES)                 { which = 0; tileIdx = b;            ntn = 16; }
    else if (b < W1_TILES + W2_TILES) { which = 1; tileIdx = b - W1_TILES; ntn = 16; }
    else                              { which = 2; tileIdx = b - W1_TILES - W2_TILES; ntn = 4; }
    const float* W = (which == 0) ? W1 : (which == 1) ? W2 : Wc;
    int N = (which == 2) ? NcOut : DH;
    int k0 = (tileIdx / ntn) * 32, n0 = (tileIdx % ntn) * 32;

    __shared__ float t[32][33];
    int tx = tid & 31, tyb = tid >> 5;
#pragma unroll
    for (int r = 0; r < 4; ++r) {
        int ty = tyb + r * 8;
        int n = n0 + tx;
        float v = 0.0f;
        if (n < N) v = W[(size_t)(k0 + ty) * N + n];
        t[ty][tx] = v;
    }
    __syncthreads();
    __nv_bfloat16 *dh, *dl;
    if (which == 0)      { dh = (__nv_bfloat16*)g_w1hi; dl = (__nv_bfloat16*)g_w1lo; }
    else if (which == 1) { dh = (__nv_bfloat16*)g_w2hi; dl = (__nv_bfloat16*)g_w2lo; }
    else                 { dh = (__nv_bfloat16*)g_wchi; dl = (__nv_bfloat16*)g_wclo; }
#pragma unroll
    for (int r = 0; r < 4; ++r) {
        int ty = tyb + r * 8;
        float w = t[tx][ty];
        __nv_bfloat16 hi, lo;
        split_bf16(w, hi, lo);
        size_t o = (size_t)(n0 + ty) * DH + (k0 + tx);
        dh[o] = hi;
        dl[o] = lo;
    }
}

// ---------------------------------------------------------------------------
// HMMA GEMM, fused split passes. 64x128 CTA tile, BK=16, 8 warps (2x4),
// warp tile 32x32, 3 CTAs/SM. Smem: 32B permuted rows, 3-stage pipeline.
// ---------------------------------------------------------------------------
#define BMt 64
#define BNt 128
#define BKt 16
#define STAGEB 12288
#define OFF_ALO 2048
#define OFF_BHI 4096
#define OFF_BLO 8192
#define NCH (DH / BKt)                // 32 k-chunks

__global__ __launch_bounds__(256, 3)
void mma_gemm_kernel(int which, const float* __restrict__ bias,
                     float* __restrict__ extout, int Nvalid)
{
    __shared__ __align__(128) char sMem[3 * STAGEB];   // 36864 B

    int tid = threadIdx.x, lane = tid & 31, wid = tid >> 5;
    int m0 = blockIdx.y * BMt, n0 = blockIdx.x * BNt;
    int warp_m = (wid >> 2) * 32, warp_n = (wid & 3) * 32;

    const uint4 *Wh, *Wl;
    if (which == 0)      { Wh = g_w1hi; Wl = g_w1lo; }
    else if (which == 1) { Wh = g_w2hi; Wl = g_w2lo; }
    else                 { Wh = g_wchi; Wl = g_wclo; }

    uint32_t base = smem_to_u32(sMem);

    int ta = tid & 127;
    int rA = ta >> 1, jA = tid & 1;
    const uint4* aSrcBase = (tid < 128) ? g_ahi : g_alo;
    uint32_t aDst = (uint32_t)((tid < 128 ? 0 : OFF_ALO) +
                               rA * 32 + ((jA ^ ((rA >> 2) & 1)) * 16));
    bool avalid = (m0 + rA) < NNODES;
    size_t aRow = (size_t)(m0 + rA) * (DH / 8) + jA;
    int rB = tid >> 1, jB = tid & 1;
    uint32_t bDst = (uint32_t)(rB * 32 + ((jB ^ ((rB >> 2) & 1)) * 16));
    size_t bRow = (size_t)(n0 + rB) * (DH / 8) + jB;

    float acc[2][4][4];
#pragma unroll
    for (int a = 0; a < 2; ++a)
#pragma unroll
        for (int b = 0; b < 4; ++b)
#pragma unroll
            for (int c = 0; c < 4; ++c) acc[a][b][c] = 0.0f;

#define ISSUE(it, buf) do {                                                  \
        size_t _ko = (size_t)(it) * 2;                                       \
        uint32_t _s = base + (buf) * STAGEB;                                 \
        cp16(_s + aDst,           aSrcBase + aRow + _ko, avalid);            \
        cp16(_s + OFF_BHI + bDst, Wh + bRow + _ko, true);                    \
        cp16(_s + OFF_BLO + bDst, Wl + bRow + _ko, true);                    \
    } while (0)

    ISSUE(0, 0);
    CP_COMMIT();
    ISSUE(1, 1);
    CP_COMMIT();

    uint32_t aFragOff[2], bFragOff[2];
#pragma unroll
    for (int mf = 0; mf < 2; ++mf) {
        int row = warp_m + mf * 16 + (lane & 15);
        int cs = (lane >> 4) ^ ((row >> 2) & 1);
        aFragOff[mf] = (uint32_t)(row * 32 + cs * 16);
    }
#pragma unroll
    for (int nb = 0; nb < 2; ++nb) {
        int nrow = warp_n + nb * 16 + ((lane >> 4) << 3) + (lane & 7);
        int cs = ((lane >> 3) & 1) ^ ((nrow >> 2) & 1);
        bFragOff[nb] = (uint32_t)(nrow * 32 + cs * 16);
    }

    int buf = 0;
    for (int it = 0; it < NCH; ++it) {
        if (it + 1 < NCH) CP_WAIT1(); else CP_WAIT0();
        __syncthreads();

        if (it + 2 < NCH) {
            int buf2 = buf + 2; if (buf2 >= 3) buf2 -= 3;
            ISSUE(it + 2, buf2);
            CP_COMMIT();
        }

        uint32_t sb = base + buf * STAGEB;
        uint32_t ahi[2][4], bhi[2][4], blo[2][4];
#pragma unroll
        for (int mf = 0; mf < 2; ++mf) ldmat_x4(ahi[mf], sb + aFragOff[mf]);
#pragma unroll
        for (int nb = 0; nb < 2; ++nb) {
            ldmat_x4(bhi[nb], sb + OFF_BHI + bFragOff[nb]);
            ldmat_x4(blo[nb], sb + OFF_BLO + bFragOff[nb]);
        }
#pragma unroll
        for (int mf = 0; mf < 2; ++mf)
#pragma unroll
            for (int nf = 0; nf < 4; ++nf)
                mma_bf16(acc[mf][nf], ahi[mf],
                         bhi[nf >> 1][(nf & 1) * 2], bhi[nf >> 1][(nf & 1) * 2 + 1]);
#pragma unroll
        for (int mf = 0; mf < 2; ++mf)
#pragma unroll
            for (int nf = 0; nf < 4; ++nf)
                mma_bf16(acc[mf][nf], ahi[mf],
                         blo[nf >> 1][(nf & 1) * 2], blo[nf >> 1][(nf & 1) * 2 + 1]);
        uint32_t alo[2][4];
#pragma unroll
        for (int mf = 0; mf < 2; ++mf) ldmat_x4(alo[mf], sb + OFF_ALO + aFragOff[mf]);
#pragma unroll
        for (int mf = 0; mf < 2; ++mf)
#pragma unroll
            for (int nf = 0; nf < 4; ++nf)
                mma_bf16(acc[mf][nf], alo[mf],
                         bhi[nf >> 1][(nf & 1) * 2], bhi[nf >> 1][(nf & 1) * 2 + 1]);

        if (++buf == 3) buf = 0;
    }
#undef ISSUE

    // epilogue
#pragma unroll
    for (int mf = 0; mf < 2; ++mf) {
        int rr = m0 + warp_m + mf * 16 + (lane >> 2);
#pragma unroll
        for (int nf = 0; nf < 4; ++nf) {
            int cc = n0 + warp_n + nf * 8 + (lane & 3) * 2;
            float d0 = acc[mf][nf][0], d1 = acc[mf][nf][1];
            float d2 = acc[mf][nf][2], d3 = acc[mf][nf][3];
            if (extout) {
                if (rr < NNODES) {
                    if (cc < Nvalid)     extout[(size_t)rr * Nvalid + cc]     = d0 + bias[cc];
                    if (cc + 1 < Nvalid) extout[(size_t)rr * Nvalid + cc + 1] = d1 + bias[cc + 1];
                }
                if (rr + 8 < NNODES) {
                    if (cc < Nvalid)     extout[(size_t)(rr + 8) * Nvalid + cc]     = d2 + bias[cc];
                    if (cc + 1 < Nvalid) extout[(size_t)(rr + 8) * Nvalid + cc + 1] = d3 + bias[cc + 1];
                }
            } else {
                if (rr < NNODES)     *(float2*)&g_h[(size_t)rr * DH + cc]       = make_float2(d0, d1);
                if (rr + 8 < NNODES) *(float2*)&g_h[(size_t)(rr + 8) * DH + cc] = make_float2(d2, d3);
            }
        }
    }
}

// ---------------------------------------------------------------------------
// Aggregation: one block per node; bucketed adjacency.
// phase 0 (after gemm1): dinv computed from g_cnt inline, persisted to g_dinv.
// phase 1 (after gemm2): dinv read from g_dinv; g_cnt[i] reset to 0 for the
//                        next graph replay (after a block-level sync).
// ---------------------------------------------------------------------------
__global__ __launch_bounds__(128) void agg_kernel(
    const float* __restrict__ bias, int relu, int phase)
{
    int i = blockIdx.x;
    int tid = threadIdx.x;
    const float4* h4 = (const float4*)g_h;

    int cnt_i = g_cnt[i];
    int deg = (cnt_i < CAP) ? cnt_i : CAP;
    float di;
    if (phase == 0) {
        di = rsqrtf(1.0f + (float)cnt_i);
        if (tid == 0) g_dinv[i] = di;
    } else {
        di = g_dinv[i];
    }
    __syncthreads();   // all reads of g_cnt[i] done before any reset below

    const int* col = &g_col[(size_t)i * CAP];
    float4 acc = make_float4(0.f, 0.f, 0.f, 0.f);
#pragma unroll 2
    for (int jj = 0; jj < deg; ++jj) {
        int s = col[jj];
        float ds = (phase == 0) ? rsqrtf(1.0f + (float)g_cnt[s]) : g_dinv[s];
        float w = ds * di;
        float4 v = h4[(size_t)s * (DH / 4) + tid];
        acc.x += v.x * w;
        acc.y += v.y * w;
        acc.z += v.z * w;
        acc.w += v.w * w;
    }
    float sw = di * di;
    float4 self = h4[(size_t)i * (DH / 4) + tid];
    acc.x += self.x * sw;
    acc.y += self.y * sw;
    acc.z += self.z * sw;
    acc.w += self.w * sw;
    const float4* b4 = (const float4*)bias;
    float4 bb = b4[tid];
    acc.x += bb.x; acc.y += bb.y; acc.z += bb.z; acc.w += bb.w;
    if (relu) {
        acc.x = fmaxf(acc.x, 0.f);
        acc.y = fmaxf(acc.y, 0.f);
        acc.z = fmaxf(acc.z, 0.f);
        acc.w = fmaxf(acc.w, 0.f);
    }
    float v[4] = {acc.x, acc.y, acc.z, acc.w};
    __nv_bfloat16 hi[4], lo[4];
#pragma unroll
    for (int jj = 0; jj < 4; ++jj) split_bf16(v[jj], hi[jj], lo[jj]);
    ((uint2*)g_ahi)[(size_t)i * (DH / 4) + tid] = *(uint2*)hi;
    ((uint2*)g_alo)[(size_t)i * (DH / 4) + tid] = *(uint2*)lo;

    if (phase == 1 && tid == 0) g_cnt[i] = 0;   // ready for next replay
}

// ---------------------------------------------------------------------------
extern "C" void kernel_launch(void* const* d_in, const int* in_sizes, int n_in,
                              void* d_out, int out_size) {
    const float* x  = (const float*)d_in[0];
    const int*   ei = (const int*)d_in[1];     // int32 (JAX x64 disabled)
    const float* W1 = (const float*)d_in[2];
    const float* b1 = (const float*)d_in[3];
    const float* W2 = (const float*)d_in[4];
    const float* b2 = (const float*)d_in[5];
    const float* Wc = (const float*)d_in[6];
    const float* bc = (const float*)d_in[7];
    float* out = (float*)d_out;

    int N = in_sizes[0] / DH;             // 10000
    int E = in_sizes[1] / 2;              // 160000
    int d_out_dim = in_sizes[6] / DH;     // 100

    // Merged prep: conv_x + bucketed fill + weight transpose/split
    prep_all_kernel<<<PREP_BLOCKS, 256>>>(x, ei, E, W1, W2, Wc, d_out_dim);

    int mblocks = (N + BMt - 1) / BMt;    // 157

    // Layer 1
    mma_gemm_kernel<<<dim3(DH / BNt, mblocks), 256>>>(0, nullptr, nullptr, DH);
    agg_kernel<<<N, 128>>>(b1, 1, 0);

    // Layer 2
    mma_gemm_kernel<<<dim3(DH / BNt, mblocks), 256>>>(1, nullptr, nullptr, DH);
    agg_kernel<<<N, 128>>>(b2, 0, 1);

    // Classifier
    mma_gemm_kernel<<<dim3(1, mblocks), 256>>>(2, bc, out, d_out_dim);
}

// round 16
// speedup vs baseline: 1.4017x; 1.4017x over previous
#include <cuda_runtime.h>
#include <cuda_bf16.h>
#include <cstdint>

// ---------------------------------------------------------------------------
// CompressedGNN on GB300 (plain sm_103 target — no tcgen05 in harness PTX).
// GEMMs: mma.sync bf16 (HMMA), split-precision x3 fused, BM=64 @ 3 CTAs/SM.
// Prep (x-split + edge-count + weight transpose/split) merged into one launch;
// scan re-zeros cnt for replays. CSR fill + gather agg as in best-known config.
// ---------------------------------------------------------------------------

#define NNODES 10000
#define MAXE   160000
#define DH     512
#define NPADC  128

__device__ float g_h[NNODES * DH];              // fp32 GEMM output
__device__ uint4 g_ahi[NNODES * DH / 8];        // split A operand (8 bf16/uint4)
__device__ uint4 g_alo[NNODES * DH / 8];
__device__ uint4 g_w1hi[DH * DH / 8];           // transposed split weights [N][K]
__device__ uint4 g_w1lo[DH * DH / 8];
__device__ uint4 g_w2hi[DH * DH / 8];
__device__ uint4 g_w2lo[DH * DH / 8];
__device__ uint4 g_wchi[NPADC * DH / 8];
__device__ uint4 g_wclo[NPADC * DH / 8];
__device__ float g_dinv[NNODES];
__device__ int   g_cnt[NNODES];                 // zero-init; re-zeroed by scan
__device__ int   g_rowptr[NNODES + 1];
__device__ int   g_cursor[NNODES];
__device__ int   g_col[MAXE];

// ---------------------------------------------------------------------------
__device__ __forceinline__ uint32_t smem_to_u32(const void* p) {
    uint32_t a;
    asm("{ .reg .u64 t; cvta.to.shared.u64 t, %1; cvt.u32.u64 %0, t; }"
        : "=r"(a) : "l"(p));
    return a;
}

__device__ __forceinline__ void ldmat_x4(uint32_t (&r)[4], uint32_t addr) {
    asm volatile("ldmatrix.sync.aligned.m8n8.x4.shared.b16 {%0,%1,%2,%3}, [%4];"
                 : "=r"(r[0]), "=r"(r[1]), "=r"(r[2]), "=r"(r[3]) : "r"(addr));
}

__device__ __forceinline__ void mma_bf16(float (&d)[4], const uint32_t (&a)[4],
                                         uint32_t b0, uint32_t b1) {
    asm volatile("mma.sync.aligned.m16n8k16.row.col.f32.bf16.bf16.f32 "
                 "{%0,%1,%2,%3}, {%4,%5,%6,%7}, {%8,%9}, {%0,%1,%2,%3};"
                 : "+f"(d[0]), "+f"(d[1]), "+f"(d[2]), "+f"(d[3])
                 : "r"(a[0]), "r"(a[1]), "r"(a[2]), "r"(a[3]), "r"(b0), "r"(b1));
}

__device__ __forceinline__ void cp16(uint32_t dst, const void* src, bool valid) {
    int sz = valid ? 16 : 0;
    asm volatile("cp.async.cg.shared.global [%0], [%1], 16, %2;"
                 :: "r"(dst), "l"(src), "r"(sz) : "memory");
}
#define CP_COMMIT() asm volatile("cp.async.commit_group;" ::: "memory")
#define CP_WAIT0()  asm volatile("cp.async.wait_group 0;" ::: "memory")
#define CP_WAIT1()  asm volatile("cp.async.wait_group 1;" ::: "memory")

// ---------------------------------------------------------------------------
__device__ __forceinline__ void split_bf16(float v, __nv_bfloat16& hi, __nv_bfloat16& lo) {
    hi = __float2bfloat16(v);
    lo = __float2bfloat16(v - __bfloat162float(hi));
}

// ---------------------------------------------------------------------------
// Merged prep:
//   [0, 2500)      conv_x: split x into g_ahi/g_alo
//   [2500, 3125)   count: indegree histogram (g_cnt arrives zeroed)
//   [3125, 3701)   weight transpose + split
// ---------------------------------------------------------------------------
#define CONV_BLOCKS 2500
#define COUNT_BLOCKS 625
#define W1_TILES 256
#define W2_TILES 256
#define WC_TILES 64
#define PREP_BLOCKS (CONV_BLOCKS + COUNT_BLOCKS + W1_TILES + W2_TILES + WC_TILES)

__global__ __launch_bounds__(256) void prep_all_kernel(
    const float* __restrict__ x, const int* __restrict__ ei, int E,
    const float* __restrict__ W1, const float* __restrict__ W2,
    const float* __restrict__ Wc, int NcOut)
{
    int b = blockIdx.x, tid = threadIdx.x;

    if (b < CONV_BLOCKS) {
        int idx = b * 256 + tid;
        const float4* p = (const float4*)x;
        float4 a = p[idx * 2], b4 = p[idx * 2 + 1];
        float v[8] = {a.x, a.y, a.z, a.w, b4.x, b4.y, b4.z, b4.w};
        __nv_bfloat16 hi[8], lo[8];
#pragma unroll
        for (int j = 0; j < 8; ++j) split_bf16(v[j], hi[j], lo[j]);
        g_ahi[idx] = *(uint4*)hi;
        g_alo[idx] = *(uint4*)lo;
        return;
    }
    b -= CONV_BLOCKS;
    if (b < COUNT_BLOCKS) {
        int e = b * 256 + tid;
        if (e < E) {
            int d = ei[E + e];
            if (d >= 0 && d < NNODES) atomicAdd(&g_cnt[d], 1);
        }
        return;
    }
    b -= COUNT_BLOCKS;

    // weight transpose + split, 32x32 tile per block, 256 threads (4 rows each)
    int which, tileIdx, ntn;
    if (b < W1_TILES)                 { which = 0; tileIdx = b;            ntn = 16; }
    else if (b < W1_TILES + W2_TILES) { which = 1; tileIdx = b - W1_TILES; ntn = 16; }
    else                              { which = 2; tileIdx = b - W1_TILES - W2_TILES; ntn = 4; }
    const float* W = (which == 0) ? W1 : (which == 1) ? W2 : Wc;
    int N = (which == 2) ? NcOut : DH;
    int k0 = (tileIdx / ntn) * 32, n0 = (tileIdx % ntn) * 32;

    __shared__ float t[32][33];
    int tx = tid & 31, tyb = tid >> 5;
#pragma unroll
    for (int r = 0; r < 4; ++r) {
        int ty = tyb + r * 8;
        int n = n0 + tx;
        float v = 0.0f;
        if (n < N) v = W[(size_t)(k0 + ty) * N + n];
        t[ty][tx] = v;
    }
    __syncthreads();
    __nv_bfloat16 *dh, *dl;
    if (which == 0)      { dh = (__nv_bfloat16*)g_w1hi; dl = (__nv_bfloat16*)g_w1lo; }
    else if (which == 1) { dh = (__nv_bfloat16*)g_w2hi; dl = (__nv_bfloat16*)g_w2lo; }
    else                 { dh = (__nv_bfloat16*)g_wchi; dl = (__nv_bfloat16*)g_wclo; }
#pragma unroll
    for (int r = 0; r < 4; ++r) {
        int ty = tyb + r * 8;
        float w = t[tx][ty];
        __nv_bfloat16 hi, lo;
        split_bf16(w, hi, lo);
        size_t o = (size_t)(n0 + ty) * DH + (k0 + tx);
        dh[o] = hi;
        dl[o] = lo;
    }
}

// ---------------------------------------------------------------------------
// Shuffle-based single-block scan (2 barriers). Re-zeros g_cnt for replays.
// ---------------------------------------------------------------------------
__global__ void scan_kernel(int n) {
    __shared__ int wsum[32], woff[32];
    int tid = threadIdx.x, lane = tid & 31, wid = tid >> 5;
    int CH = (n + 1023) >> 10;           // 10 for n=10000
    int base = tid * CH;
    int cl[16];
    int s = 0;
#pragma unroll 10
    for (int i = 0; i < CH; ++i) {
        int idx = base + i;
        int c = 0;
        if (idx < n) {
            c = g_cnt[idx];
            g_cnt[idx] = 0;              // ready for next replay's count pass
        }
        cl[i] = c;
        s += c;
    }
    int mysum = s;
#pragma unroll
    for (int off = 1; off < 32; off <<= 1) {
        int v = __shfl_up_sync(0xffffffffu, s, off);
        if (lane >= off) s += v;
    }
    if (lane == 31) wsum[wid] = s;
    __syncthreads();
    if (wid == 0) {
        int t0 = wsum[lane];
        int ts = t0;
#pragma unroll
        for (int off = 1; off < 32; off <<= 1) {
            int v = __shfl_up_sync(0xffffffffu, ts, off);
            if (lane >= off) ts += v;
        }
        woff[lane] = ts - t0;
        if (lane == 31) g_rowptr[n] = ts;
    }
    __syncthreads();
    int run = woff[wid] + (s - mysum);
#pragma unroll 10
    for (int i = 0; i < CH; ++i) {
        int idx = base + i;
        if (idx < n) {
            g_rowptr[idx] = run;
            g_cursor[idx] = run;
            int c = cl[i];
            g_dinv[idx] = rsqrtf(1.0f + (float)c);
            run += c;
        }
    }
}

__global__ void fill_kernel(const int* __restrict__ ei, int E, int n) {
    int e = blockIdx.x * blockDim.x + threadIdx.x;
    if (e < E) {
        int s = ei[e];
        int d = ei[E + e];
        if (d >= 0 && d < n && s >= 0 && s < n) {
            int pos = atomicAdd(&g_cursor[d], 1);
            g_col[pos] = s;
        }
    }
}

// ---------------------------------------------------------------------------
// HMMA GEMM, fused split passes. 64x128 CTA tile, BK=16, 8 warps (2x4),
// warp tile 32x32, 3 CTAs/SM. Smem: 32B permuted rows, 3-stage pipeline.
// ---------------------------------------------------------------------------
#define BMt 64
#define BNt 128
#define BKt 16
#define STAGEB 12288
#define OFF_ALO 2048
#define OFF_BHI 4096
#define OFF_BLO 8192
#define NCH (DH / BKt)                // 32 k-chunks

__global__ __launch_bounds__(256, 3)
void mma_gemm_kernel(int which, const float* __restrict__ bias,
                     float* __restrict__ extout, int Nvalid)
{
    __shared__ __align__(128) char sMem[3 * STAGEB];   // 36864 B

    int tid = threadIdx.x, lane = tid & 31, wid = tid >> 5;
    int m0 = blockIdx.y * BMt, n0 = blockIdx.x * BNt;
    int warp_m = (wid >> 2) * 32, warp_n = (wid & 3) * 32;

    const uint4 *Wh, *Wl;
    if (which == 0)      { Wh = g_w1hi; Wl = g_w1lo; }
    else if (which == 1) { Wh = g_w2hi; Wl = g_w2lo; }
    else                 { Wh = g_wchi; Wl = g_wclo; }

    uint32_t base = smem_to_u32(sMem);

    int ta = tid & 127;
    int rA = ta >> 1, jA = tid & 1;
    const uint4* aSrcBase = (tid < 128) ? g_ahi : g_alo;
    uint32_t aDst = (uint32_t)((tid < 128 ? 0 : OFF_ALO) +
                               rA * 32 + ((jA ^ ((rA >> 2) & 1)) * 16));
    bool avalid = (m0 + rA) < NNODES;
    size_t aRow = (size_t)(m0 + rA) * (DH / 8) + jA;
    int rB = tid >> 1, jB = tid & 1;
    uint32_t bDst = (uint32_t)(rB * 32 + ((jB ^ ((rB >> 2) & 1)) * 16));
    size_t bRow = (size_t)(n0 + rB) * (DH / 8) + jB;

    float acc[2][4][4];
#pragma unroll
    for (int a = 0; a < 2; ++a)
#pragma unroll
        for (int b = 0; b < 4; ++b)
#pragma unroll
            for (int c = 0; c < 4; ++c) acc[a][b][c] = 0.0f;

#define ISSUE(it, buf) do {                                                  \
        size_t _ko = (size_t)(it) * 2;                                       \
        uint32_t _s = base + (buf) * STAGEB;                                 \
        cp16(_s + aDst,           aSrcBase + aRow + _ko, avalid);            \
        cp16(_s + OFF_BHI + bDst, Wh + bRow + _ko, true);                    \
        cp16(_s + OFF_BLO + bDst, Wl + bRow + _ko, true);                    \
    } while (0)

    ISSUE(0, 0);
    CP_COMMIT();
    ISSUE(1, 1);
    CP_COMMIT();

    uint32_t aFragOff[2], bFragOff[2];
#pragma unroll
    for (int mf = 0; mf < 2; ++mf) {
        int row = warp_m + mf * 16 + (lane & 15);
        int cs = (lane >> 4) ^ ((row >> 2) & 1);
        aFragOff[mf] = (uint32_t)(row * 32 + cs * 16);
    }
#pragma unroll
    for (int nb = 0; nb < 2; ++nb) {
        int nrow = warp_n + nb * 16 + ((lane >> 4) << 3) + (lane & 7);
        int cs = ((lane >> 3) & 1) ^ ((nrow >> 2) & 1);
        bFragOff[nb] = (uint32_t)(nrow * 32 + cs * 16);
    }

    int buf = 0;
    for (int it = 0; it < NCH; ++it) {
        if (it + 1 < NCH) CP_WAIT1(); else CP_WAIT0();
        __syncthreads();

        if (it + 2 < NCH) {
            int buf2 = buf + 2; if (buf2 >= 3) buf2 -= 3;
            ISSUE(it + 2, buf2);
            CP_COMMIT();
        }

        uint32_t sb = base + buf * STAGEB;
        uint32_t ahi[2][4], bhi[2][4], blo[2][4];
#pragma unroll
        for (int mf = 0; mf < 2; ++mf) ldmat_x4(ahi[mf], sb + aFragOff[mf]);
#pragma unroll
        for (int nb = 0; nb < 2; ++nb) {
            ldmat_x4(bhi[nb], sb + OFF_BHI + bFragOff[nb]);
            ldmat_x4(blo[nb], sb + OFF_BLO + bFragOff[nb]);
        }
#pragma unroll
        for (int mf = 0; mf < 2; ++mf)
#pragma unroll
            for (int nf = 0; nf < 4; ++nf)
                mma_bf16(acc[mf][nf], ahi[mf],
                         bhi[nf >> 1][(nf & 1) * 2], bhi[nf >> 1][(nf & 1) * 2 + 1]);
#pragma unroll
        for (int mf = 0; mf < 2; ++mf)
#pragma unroll
            for (int nf = 0; nf < 4; ++nf)
                mma_bf16(acc[mf][nf], ahi[mf],
                         blo[nf >> 1][(nf & 1) * 2], blo[nf >> 1][(nf & 1) * 2 + 1]);
        uint32_t alo[2][4];
#pragma unroll
        for (int mf = 0; mf < 2; ++mf) ldmat_x4(alo[mf], sb + OFF_ALO + aFragOff[mf]);
#pragma unroll
        for (int mf = 0; mf < 2; ++mf)
#pragma unroll
            for (int nf = 0; nf < 4; ++nf)
                mma_bf16(acc[mf][nf], alo[mf],
                         bhi[nf >> 1][(nf & 1) * 2], bhi[nf >> 1][(nf & 1) * 2 + 1]);

        if (++buf == 3) buf = 0;
    }
#undef ISSUE

    // epilogue
#pragma unroll
    for (int mf = 0; mf < 2; ++mf) {
        int rr = m0 + warp_m + mf * 16 + (lane >> 2);
#pragma unroll
        for (int nf = 0; nf < 4; ++nf) {
            int cc = n0 + warp_n + nf * 8 + (lane & 3) * 2;
            float d0 = acc[mf][nf][0], d1 = acc[mf][nf][1];
            float d2 = acc[mf][nf][2], d3 = acc[mf][nf][3];
            if (extout) {
                if (rr < NNODES) {
                    if (cc < Nvalid)     extout[(size_t)rr * Nvalid + cc]     = d0 + bias[cc];
                    if (cc + 1 < Nvalid) extout[(size_t)rr * Nvalid + cc + 1] = d1 + bias[cc + 1];
                }
                if (rr + 8 < NNODES) {
                    if (cc < Nvalid)     extout[(size_t)(rr + 8) * Nvalid + cc]     = d2 + bias[cc];
                    if (cc + 1 < Nvalid) extout[(size_t)(rr + 8) * Nvalid + cc + 1] = d3 + bias[cc + 1];
                }
            } else {
                if (rr < NNODES)     *(float2*)&g_h[(size_t)rr * DH + cc]       = make_float2(d0, d1);
                if (rr + 8 < NNODES) *(float2*)&g_h[(size_t)(rr + 8) * DH + cc] = make_float2(d2, d3);
            }
        }
    }
}

// ---------------------------------------------------------------------------
// Aggregation: one block per node; writes split bf16 for next GEMM.
// ---------------------------------------------------------------------------
__global__ __launch_bounds__(128) void agg_kernel(
    const float* __restrict__ bias, int relu)
{
    int i = blockIdx.x;
    int tid = threadIdx.x;
    const float4* h4 = (const float4*)g_h;
    float di = g_dinv[i];
    int beg = g_rowptr[i];
    int end = g_rowptr[i + 1];

    float4 acc = make_float4(0.f, 0.f, 0.f, 0.f);
#pragma unroll 2
    for (int jj = beg; jj < end; ++jj) {
        int s = g_col[jj];
        float w = g_dinv[s] * di;
        float4 v = h4[(size_t)s * (DH / 4) + tid];
        acc.x += v.x * w;
        acc.y += v.y * w;
        acc.z += v.z * w;
        acc.w += v.w * w;
    }
    float sw = di * di;
    float4 self = h4[(size_t)i * (DH / 4) + tid];
    acc.x += self.x * sw;
    acc.y += self.y * sw;
    acc.z += self.z * sw;
    acc.w += self.w * sw;
    const float4* b4 = (const float4*)bias;
    float4 bb = b4[tid];
    acc.x += bb.x; acc.y += bb.y; acc.z += bb.z; acc.w += bb.w;
    if (relu) {
        acc.x = fmaxf(acc.x, 0.f);
        acc.y = fmaxf(acc.y, 0.f);
        acc.z = fmaxf(acc.z, 0.f);
        acc.w = fmaxf(acc.w, 0.f);
    }
    float v[4] = {acc.x, acc.y, acc.z, acc.w};
    __nv_bfloat16 hi[4], lo[4];
#pragma unroll
    for (int jj = 0; jj < 4; ++jj) split_bf16(v[jj], hi[jj], lo[jj]);
    ((uint2*)g_ahi)[(size_t)i * (DH / 4) + tid] = *(uint2*)hi;
    ((uint2*)g_alo)[(size_t)i * (DH / 4) + tid] = *(uint2*)lo;
}

// ---------------------------------------------------------------------------
extern "C" void kernel_launch(void* const* d_in, const int* in_sizes, int n_in,
                              void* d_out, int out_size) {
    const float* x  = (const float*)d_in[0];
    const int*   ei = (const int*)d_in[1];     // int32 (JAX x64 disabled)
    const float* W1 = (const float*)d_in[2];
    const float* b1 = (const float*)d_in[3];
    const float* W2 = (const float*)d_in[4];
    const float* b2 = (const float*)d_in[5];
    const float* Wc = (const float*)d_in[6];
    const float* bc = (const float*)d_in[7];
    float* out = (float*)d_out;

    int N = in_sizes[0] / DH;             // 10000
    int E = in_sizes[1] / 2;              // 160000
    int d_out_dim = in_sizes[6] / DH;     // 100

    // Merged prep: conv_x + indegree count + weight transpose/split
    prep_all_kernel<<<PREP_BLOCKS, 256>>>(x, ei, E, W1, W2, Wc, d_out_dim);

    // CSR build (scan re-zeros cnt for graph replays)
    scan_kernel<<<1, 1024>>>(N);
    fill_kernel<<<(E + 255) / 256, 256>>>(ei, E, N);

    int mblocks = (N + BMt - 1) / BMt;    // 157

    // Layer 1
    mma_gemm_kernel<<<dim3(DH / BNt, mblocks), 256>>>(0, nullptr, nullptr, DH);
    agg_kernel<<<N, 128>>>(b1, 1);

    // Layer 2
    mma_gemm_kernel<<<dim3(DH / BNt, mblocks), 256>>>(1, nullptr, nullptr, DH);
    agg_kernel<<<N, 128>>>(b2, 0);

    // Classifier
    mma_gemm_kernel<<<dim3(1, mblocks), 256>>>(2, bc, out, d_out_dim);
}